// round 1
// baseline (speedup 1.0000x reference)
#include <cuda_runtime.h>
#include <cstdint>

// SimpleGRU — persistent batch-parallel fp32 SIMT kernel.
// B=4096, S=64, IN=1, H=256, TL=42 (TL derived from out_size on host).
//
// One CTA handles TB=32 batch rows through the full 64-step encoder,
// the single decoder-GEMM (gh_dec), and the 42-step cheap decoder.
// Heavy op per step: gh[32,768] = h[32,256] @ w_hh^T, staged through
// double-buffered cp.async SMEM tiles of w_hh.

#define HDIM     256
#define THREE_H  768
#define SEQ      64
#define TB       32          // batch rows per CTA
#define NTHREADS 256
#define KB       16          // k-block depth
#define WROW     20          // padded W stage row (floats), 80B = 5*16B aligned
#define HROW     260         // padded h row (floats)
#define WSTAGE   (THREE_H * WROW)

__device__ __forceinline__ float sigf(float v) {
    return __fdividef(1.0f, 1.0f + __expf(-v));
}
__device__ __forceinline__ float tanhf2(float v) {
    // tanh(x) = 2*sigmoid(2x) - 1  (accurate: __expf err ~1e-6 rel)
    return fmaf(2.0f, sigf(2.0f * v), -1.0f);
}

__device__ __forceinline__ void issue_block(const float* __restrict__ w_hh,
                                            float* dstbase, int kb, int tid) {
    // stage w_hh[:, kb*16 .. kb*16+15] -> [768][WROW] smem tile. 3072 16B chunks.
#pragma unroll
    for (int r = 0; r < 12; r++) {
        int ch = tid + r * NTHREADS;       // 0..3071
        int j  = ch >> 2;
        int q  = ch & 3;
        const float* src = w_hh + j * HDIM + kb * KB + q * 4;
        unsigned d = (unsigned)__cvta_generic_to_shared(dstbase + j * WROW + q * 4);
        asm volatile("cp.async.cg.shared.global [%0], [%1], 16;\n" :: "r"(d), "l"(src));
    }
    asm volatile("cp.async.commit_group;\n");
}

// One full GEMM step: acc[ci][g][i] = sum_k w_hh[g*256 + c][k] * h[b0+i][k]
// with c = cl + ci*64, b0 = bg*8.
__device__ __forceinline__ void gemm_step(const float* __restrict__ w_hh,
                                          float* Wbuf, const float* __restrict__ rb,
                                          int tid, int bg, int cl,
                                          float (&acc)[4][3][8]) {
#pragma unroll
    for (int ci = 0; ci < 4; ci++)
#pragma unroll
        for (int g = 0; g < 3; g++)
#pragma unroll
            for (int i = 0; i < 8; i++) acc[ci][g][i] = 0.0f;

    issue_block(w_hh, Wbuf, 0, tid);

#pragma unroll 1
    for (int kb = 0; kb < HDIM / KB; kb++) {
        if (kb < HDIM / KB - 1) {
            issue_block(w_hh, Wbuf + ((kb + 1) & 1) * WSTAGE, kb + 1, tid);
            asm volatile("cp.async.wait_group 1;\n");
        } else {
            asm volatile("cp.async.wait_group 0;\n");
        }
        __syncthreads();   // all threads' staged data visible

        const float* cur = Wbuf + (kb & 1) * WSTAGE;
#pragma unroll 2
        for (int kq = 0; kq < 4; kq++) {
            float4 hq[8];
#pragma unroll
            for (int i = 0; i < 8; i++)
                hq[i] = *reinterpret_cast<const float4*>(
                    &rb[(bg * 8 + i) * HROW + kb * KB + kq * 4]);
#pragma unroll
            for (int ci = 0; ci < 4; ci++) {
                int c = cl + ci * 64;
#pragma unroll
                for (int g = 0; g < 3; g++) {
                    const float4 wq = *reinterpret_cast<const float4*>(
                        &cur[(g * 256 + c) * WROW + kq * 4]);
#pragma unroll
                    for (int i = 0; i < 8; i++) {
                        float a = acc[ci][g][i];
                        a = fmaf(wq.x, hq[i].x, a);
                        a = fmaf(wq.y, hq[i].y, a);
                        a = fmaf(wq.z, hq[i].z, a);
                        a = fmaf(wq.w, hq[i].w, a);
                        acc[ci][g][i] = a;
                    }
                }
            }
        }
        __syncthreads();   // tile fully consumed before next overwrite
    }
}

__global__ __launch_bounds__(NTHREADS, 1)
void gru_kernel(const float* __restrict__ gx, const float* __restrict__ w_ih,
                const float* __restrict__ w_hh, const float* __restrict__ b_ih,
                const float* __restrict__ b_hh, const float* __restrict__ w_out,
                const float* __restrict__ b_out, float* __restrict__ out, int TL) {
    extern __shared__ float sm[];
    float* h0     = sm;                        // [TB][HROW]
    float* h1     = h0 + TB * HROW;            // [TB][HROW]
    float* Wbuf   = h1 + TB * HROW;            // 2 * [768][WROW]
    float* u_s    = Wbuf + 2 * WSTAGE;         // [768]  (w_ih[:,0])
    float* bih_s  = u_s + THREE_H;             // [768]
    float* bhh_s  = bih_s + THREE_H;           // [768]
    float* wout_s = bhh_s + THREE_H;           // [256]
    float* x_s    = wout_s + HDIM;             // [TB][SEQ]
    float* red    = x_s + TB * SEQ;            // [TB][72]
    float* outs   = red + TB * 72;             // [TB]

    const int tid = threadIdx.x;
    const int bg  = tid >> 6;     // 0..3 -> batch group of 8
    const int cl  = tid & 63;     // 0..63 -> hidden-unit lane
    const int b0  = bg * 8;
    const int gb0 = blockIdx.x * TB;

    // ---- init: zero h0, cache params + x tile ----
    for (int i = tid; i < TB * HROW; i += NTHREADS) h0[i] = 0.0f;
    for (int i = tid; i < THREE_H; i += NTHREADS) {
        u_s[i]   = w_ih[i];     // [3H,1] contiguous
        bih_s[i] = b_ih[i];
        bhh_s[i] = b_hh[i];
    }
    for (int i = tid; i < HDIM; i += NTHREADS) wout_s[i] = w_out[i];
    for (int i = tid; i < TB * SEQ; i += NTHREADS) {
        int b = i >> 6, t = i & 63;
        x_s[i] = gx[(gb0 + b) * SEQ + t];
    }
    __syncthreads();

    float acc[4][3][8];

    // ---- encoder: 64 GRU steps, h ping-pongs h0 <-> h1 ----
#pragma unroll 1
    for (int t = 0; t < SEQ; t++) {
        const float* rb = (t & 1) ? h1 : h0;
        float*       wb = (t & 1) ? h0 : h1;
        gemm_step(w_hh, Wbuf, rb, tid, bg, cl, acc);
#pragma unroll
        for (int ci = 0; ci < 4; ci++) {
            int c = cl + ci * 64;
            float ur = u_s[c], uz = u_s[c + 256], un = u_s[c + 512];
            float br = bih_s[c] + bhh_s[c];
            float bz = bih_s[c + 256] + bhh_s[c + 256];
            float bin = bih_s[c + 512], bhn = bhh_s[c + 512];
#pragma unroll
            for (int i = 0; i < 8; i++) {
                int b = b0 + i;
                float xv = x_s[b * SEQ + t];
                float r = sigf(fmaf(xv, ur, br) + acc[ci][0][i]);
                float z = sigf(fmaf(xv, uz, bz) + acc[ci][1][i]);
                float n = tanhf2(fmaf(xv, un, bin) + r * (acc[ci][2][i] + bhn));
                float hold = rb[b * HROW + c];
                wb[b * HROW + c] = fmaf(z, hold - n, n);   // (1-z)*n + z*h
            }
        }
        __syncthreads();
    }
    // SEQ=64 even -> final hidden lives in h0.

    // ---- gh_dec = w_hh @ hidden + b_hh  (kept in registers as acc) ----
    gemm_step(w_hh, Wbuf, h0, tid, bg, cl, acc);
#pragma unroll
    for (int ci = 0; ci < 4; ci++) {
        int c = cl + ci * 64;
#pragma unroll
        for (int g = 0; g < 3; g++)
#pragma unroll
            for (int i = 0; i < 8; i++)
                acc[ci][g][i] += bhh_s[g * 256 + c];
    }
    // h_t working buffer = h1, init to hidden
    for (int i = tid; i < TB * HROW; i += NTHREADS) h1[i] = h0[i];
    __syncthreads();

    // ---- decoder: TL cheap steps ----
#pragma unroll 1
    for (int t = 0; t < TL; t++) {
        // out[b] = dot(w_out, h_t[b]) + b_out  (64-lane tree reduction per b)
#pragma unroll
        for (int i = 0; i < 8; i++) {
            int b = b0 + i;
            float p = 0.0f;
#pragma unroll
            for (int ci = 0; ci < 4; ci++) {
                int c = cl + ci * 64;
                p = fmaf(wout_s[c], h1[b * HROW + c], p);
            }
            red[b * 72 + cl] = p;
        }
        __syncthreads();
        {
            int b = tid >> 3, seg = tid & 7;
            float s = 0.0f;
#pragma unroll
            for (int j = 0; j < 8; j++) s += red[b * 72 + seg * 8 + j];
            red[b * 72 + 64 + seg] = s;
        }
        __syncthreads();
        if (tid < TB) {
            float s = 0.0f;
#pragma unroll
            for (int j = 0; j < 8; j++) s += red[tid * 72 + 64 + j];
            float o = s + b_out[0];
            outs[tid] = o;
            out[(gb0 + tid) * TL + t] = o;
        }
        __syncthreads();
        // h_{t+1} = gru_cell(out, hidden) with fixed gh_dec (acc)
#pragma unroll
        for (int ci = 0; ci < 4; ci++) {
            int c = cl + ci * 64;
            float ur = u_s[c], uz = u_s[c + 256], un = u_s[c + 512];
            float bir = bih_s[c], biz = bih_s[c + 256], bin = bih_s[c + 512];
#pragma unroll
            for (int i = 0; i < 8; i++) {
                int b = b0 + i;
                float xv = outs[b];
                float r = sigf(fmaf(xv, ur, bir) + acc[ci][0][i]);
                float z = sigf(fmaf(xv, uz, biz) + acc[ci][1][i]);
                float n = tanhf2(fmaf(xv, un, bin) + r * acc[ci][2][i]);
                float hid = h0[b * HROW + c];
                h1[b * HROW + c] = fmaf(z, hid - n, n);
            }
        }
        __syncthreads();
    }
}

extern "C" void kernel_launch(void* const* d_in, const int* in_sizes, int n_in,
                              void* d_out, int out_size) {
    const float* x     = (const float*)d_in[0];
    const float* w_ih  = (const float*)d_in[1];
    const float* w_hh  = (const float*)d_in[2];
    const float* b_ih  = (const float*)d_in[3];
    const float* b_hh  = (const float*)d_in[4];
    const float* w_out = (const float*)d_in[5];
    const float* b_out = (const float*)d_in[6];
    float* out = (float*)d_out;

    int B  = in_sizes[0] / SEQ;        // x has B*S*1 elements
    int TL = out_size / B;             // output is [B, TL, 1]

    int smem_floats = 2 * TB * HROW + 2 * WSTAGE + 3 * THREE_H + HDIM +
                      TB * SEQ + TB * 72 + TB;
    int smem_bytes = smem_floats * (int)sizeof(float);

    cudaFuncSetAttribute(gru_kernel, cudaFuncAttributeMaxDynamicSharedMemorySize,
                         smem_bytes);
    gru_kernel<<<B / TB, NTHREADS, smem_bytes>>>(x, w_ih, w_hh, b_ih, b_hh,
                                                 w_out, b_out, out, TL);
}

// round 2
// speedup vs baseline: 1.0013x; 1.0013x over previous
#include <cuda_runtime.h>
#include <cstdint>

// SimpleGRU — persistent batch-parallel fp32 SIMT kernel.
// B=4096, S=64, IN=1, H=256, TL=42 (TL derived from out_size on host).
//
// One CTA handles TB=32 batch rows through the full 64-step encoder,
// the single decoder-GEMM (gh_dec), and the 42-step cheap decoder.
// Heavy op per step: gh[32,768] = h[32,256] @ w_hh^T, staged through
// double-buffered cp.async SMEM tiles of w_hh.

#define HDIM     256
#define THREE_H  768
#define SEQ      64
#define TB       32          // batch rows per CTA
#define NTHREADS 256
#define KB       16          // k-block depth
#define WROW     20          // padded W stage row (floats), 80B = 5*16B aligned
#define HROW     260         // padded h row (floats)
#define WSTAGE   (THREE_H * WROW)

__device__ __forceinline__ float sigf(float v) {
    return __fdividef(1.0f, 1.0f + __expf(-v));
}
__device__ __forceinline__ float tanhf2(float v) {
    // tanh(x) = 2*sigmoid(2x) - 1  (accurate: __expf err ~1e-6 rel)
    return fmaf(2.0f, sigf(2.0f * v), -1.0f);
}

__device__ __forceinline__ void issue_block(const float* __restrict__ w_hh,
                                            float* dstbase, int kb, int tid) {
    // stage w_hh[:, kb*16 .. kb*16+15] -> [768][WROW] smem tile. 3072 16B chunks.
#pragma unroll
    for (int r = 0; r < 12; r++) {
        int ch = tid + r * NTHREADS;       // 0..3071
        int j  = ch >> 2;
        int q  = ch & 3;
        const float* src = w_hh + j * HDIM + kb * KB + q * 4;
        unsigned d = (unsigned)__cvta_generic_to_shared(dstbase + j * WROW + q * 4);
        asm volatile("cp.async.cg.shared.global [%0], [%1], 16;\n" :: "r"(d), "l"(src));
    }
    asm volatile("cp.async.commit_group;\n");
}

// One full GEMM step: acc[ci][g][i] = sum_k w_hh[g*256 + c][k] * h[b0+i][k]
// with c = cl + ci*64, b0 = bg*8.
__device__ __forceinline__ void gemm_step(const float* __restrict__ w_hh,
                                          float* Wbuf, const float* __restrict__ rb,
                                          int tid, int bg, int cl,
                                          float (&acc)[4][3][8]) {
#pragma unroll
    for (int ci = 0; ci < 4; ci++)
#pragma unroll
        for (int g = 0; g < 3; g++)
#pragma unroll
            for (int i = 0; i < 8; i++) acc[ci][g][i] = 0.0f;

    issue_block(w_hh, Wbuf, 0, tid);

#pragma unroll 1
    for (int kb = 0; kb < HDIM / KB; kb++) {
        if (kb < HDIM / KB - 1) {
            issue_block(w_hh, Wbuf + ((kb + 1) & 1) * WSTAGE, kb + 1, tid);
            asm volatile("cp.async.wait_group 1;\n");
        } else {
            asm volatile("cp.async.wait_group 0;\n");
        }
        __syncthreads();   // all threads' staged data visible

        const float* cur = Wbuf + (kb & 1) * WSTAGE;
#pragma unroll 2
        for (int kq = 0; kq < 4; kq++) {
            float4 hq[8];
#pragma unroll
            for (int i = 0; i < 8; i++)
                hq[i] = *reinterpret_cast<const float4*>(
                    &rb[(bg * 8 + i) * HROW + kb * KB + kq * 4]);
#pragma unroll
            for (int ci = 0; ci < 4; ci++) {
                int c = cl + ci * 64;
#pragma unroll
                for (int g = 0; g < 3; g++) {
                    const float4 wq = *reinterpret_cast<const float4*>(
                        &cur[(g * 256 + c) * WROW + kq * 4]);
#pragma unroll
                    for (int i = 0; i < 8; i++) {
                        float a = acc[ci][g][i];
                        a = fmaf(wq.x, hq[i].x, a);
                        a = fmaf(wq.y, hq[i].y, a);
                        a = fmaf(wq.z, hq[i].z, a);
                        a = fmaf(wq.w, hq[i].w, a);
                        acc[ci][g][i] = a;
                    }
                }
            }
        }
        __syncthreads();   // tile fully consumed before next overwrite
    }
}

__global__ __launch_bounds__(NTHREADS, 1)
void gru_kernel(const float* __restrict__ gx, const float* __restrict__ w_ih,
                const float* __restrict__ w_hh, const float* __restrict__ b_ih,
                const float* __restrict__ b_hh, const float* __restrict__ w_out,
                const float* __restrict__ b_out, float* __restrict__ out, int TL) {
    extern __shared__ float sm[];
    float* h0     = sm;                        // [TB][HROW]
    float* h1     = h0 + TB * HROW;            // [TB][HROW]
    float* Wbuf   = h1 + TB * HROW;            // 2 * [768][WROW]
    float* u_s    = Wbuf + 2 * WSTAGE;         // [768]  (w_ih[:,0])
    float* bih_s  = u_s + THREE_H;             // [768]
    float* bhh_s  = bih_s + THREE_H;           // [768]
    float* wout_s = bhh_s + THREE_H;           // [256]
    float* x_s    = wout_s + HDIM;             // [TB][SEQ]
    float* red    = x_s + TB * SEQ;            // [TB][72]
    float* outs   = red + TB * 72;             // [TB]

    const int tid = threadIdx.x;
    const int bg  = tid >> 6;     // 0..3 -> batch group of 8
    const int cl  = tid & 63;     // 0..63 -> hidden-unit lane
    const int b0  = bg * 8;
    const int gb0 = blockIdx.x * TB;

    // ---- init: zero h0, cache params + x tile ----
    for (int i = tid; i < TB * HROW; i += NTHREADS) h0[i] = 0.0f;
    for (int i = tid; i < THREE_H; i += NTHREADS) {
        u_s[i]   = w_ih[i];     // [3H,1] contiguous
        bih_s[i] = b_ih[i];
        bhh_s[i] = b_hh[i];
    }
    for (int i = tid; i < HDIM; i += NTHREADS) wout_s[i] = w_out[i];
    for (int i = tid; i < TB * SEQ; i += NTHREADS) {
        int b = i >> 6, t = i & 63;
        x_s[i] = gx[(gb0 + b) * SEQ + t];
    }
    __syncthreads();

    float acc[4][3][8];

    // ---- encoder: 64 GRU steps, h ping-pongs h0 <-> h1 ----
#pragma unroll 1
    for (int t = 0; t < SEQ; t++) {
        const float* rb = (t & 1) ? h1 : h0;
        float*       wb = (t & 1) ? h0 : h1;
        gemm_step(w_hh, Wbuf, rb, tid, bg, cl, acc);
#pragma unroll
        for (int ci = 0; ci < 4; ci++) {
            int c = cl + ci * 64;
            float ur = u_s[c], uz = u_s[c + 256], un = u_s[c + 512];
            float br = bih_s[c] + bhh_s[c];
            float bz = bih_s[c + 256] + bhh_s[c + 256];
            float bin = bih_s[c + 512], bhn = bhh_s[c + 512];
#pragma unroll
            for (int i = 0; i < 8; i++) {
                int b = b0 + i;
                float xv = x_s[b * SEQ + t];
                float r = sigf(fmaf(xv, ur, br) + acc[ci][0][i]);
                float z = sigf(fmaf(xv, uz, bz) + acc[ci][1][i]);
                float n = tanhf2(fmaf(xv, un, bin) + r * (acc[ci][2][i] + bhn));
                float hold = rb[b * HROW + c];
                wb[b * HROW + c] = fmaf(z, hold - n, n);   // (1-z)*n + z*h
            }
        }
        __syncthreads();
    }
    // SEQ=64 even -> final hidden lives in h0.

    // ---- gh_dec = w_hh @ hidden + b_hh  (kept in registers as acc) ----
    gemm_step(w_hh, Wbuf, h0, tid, bg, cl, acc);
#pragma unroll
    for (int ci = 0; ci < 4; ci++) {
        int c = cl + ci * 64;
#pragma unroll
        for (int g = 0; g < 3; g++)
#pragma unroll
            for (int i = 0; i < 8; i++)
                acc[ci][g][i] += bhh_s[g * 256 + c];
    }
    // h_t working buffer = h1, init to hidden
    for (int i = tid; i < TB * HROW; i += NTHREADS) h1[i] = h0[i];
    __syncthreads();

    // ---- decoder: TL cheap steps ----
#pragma unroll 1
    for (int t = 0; t < TL; t++) {
        // out[b] = dot(w_out, h_t[b]) + b_out  (64-lane tree reduction per b)
#pragma unroll
        for (int i = 0; i < 8; i++) {
            int b = b0 + i;
            float p = 0.0f;
#pragma unroll
            for (int ci = 0; ci < 4; ci++) {
                int c = cl + ci * 64;
                p = fmaf(wout_s[c], h1[b * HROW + c], p);
            }
            red[b * 72 + cl] = p;
        }
        __syncthreads();
        {
            int b = tid >> 3, seg = tid & 7;
            float s = 0.0f;
#pragma unroll
            for (int j = 0; j < 8; j++) s += red[b * 72 + seg * 8 + j];
            red[b * 72 + 64 + seg] = s;
        }
        __syncthreads();
        if (tid < TB) {
            float s = 0.0f;
#pragma unroll
            for (int j = 0; j < 8; j++) s += red[tid * 72 + 64 + j];
            float o = s + b_out[0];
            outs[tid] = o;
            out[(gb0 + tid) * TL + t] = o;
        }
        __syncthreads();
        // h_{t+1} = gru_cell(out, hidden) with fixed gh_dec (acc)
#pragma unroll
        for (int ci = 0; ci < 4; ci++) {
            int c = cl + ci * 64;
            float ur = u_s[c], uz = u_s[c + 256], un = u_s[c + 512];
            float bir = bih_s[c], biz = bih_s[c + 256], bin = bih_s[c + 512];
#pragma unroll
            for (int i = 0; i < 8; i++) {
                int b = b0 + i;
                float xv = outs[b];
                float r = sigf(fmaf(xv, ur, bir) + acc[ci][0][i]);
                float z = sigf(fmaf(xv, uz, biz) + acc[ci][1][i]);
                float n = tanhf2(fmaf(xv, un, bin) + r * acc[ci][2][i]);
                float hid = h0[b * HROW + c];
                h1[b * HROW + c] = fmaf(z, hid - n, n);
            }
        }
        __syncthreads();
    }
}

extern "C" void kernel_launch(void* const* d_in, const int* in_sizes, int n_in,
                              void* d_out, int out_size) {
    const float* x     = (const float*)d_in[0];
    const float* w_ih  = (const float*)d_in[1];
    const float* w_hh  = (const float*)d_in[2];
    const float* b_ih  = (const float*)d_in[3];
    const float* b_hh  = (const float*)d_in[4];
    const float* w_out = (const float*)d_in[5];
    const float* b_out = (const float*)d_in[6];
    float* out = (float*)d_out;

    int B  = in_sizes[0] / SEQ;        // x has B*S*1 elements
    int TL = out_size / B;             // output is [B, TL, 1]

    int smem_floats = 2 * TB * HROW + 2 * WSTAGE + 3 * THREE_H + HDIM +
                      TB * SEQ + TB * 72 + TB;
    int smem_bytes = smem_floats * (int)sizeof(float);

    cudaFuncSetAttribute(gru_kernel, cudaFuncAttributeMaxDynamicSharedMemorySize,
                         smem_bytes);
    gru_kernel<<<B / TB, NTHREADS, smem_bytes>>>(x, w_ih, w_hh, b_ih, b_hh,
                                                 w_out, b_out, out, TL);
}

// round 3
// speedup vs baseline: 1.0021x; 1.0008x over previous
#include <cuda_runtime.h>
#include <cstdint>

// SimpleGRU — persistent batch-parallel fp32 SIMT kernel.
// B=4096, S=64, IN=1, H=256, TL=42 (TL derived from out_size on host).
//
// One CTA handles TB=32 batch rows through the full 64-step encoder,
// the single decoder-GEMM (gh_dec), and the 42-step cheap decoder.
// Heavy op per step: gh[32,768] = h[32,256] @ w_hh^T, staged through
// double-buffered cp.async SMEM tiles of w_hh.

#define HDIM     256
#define THREE_H  768
#define SEQ      64
#define TB       32          // batch rows per CTA
#define NTHREADS 256
#define KB       16          // k-block depth
#define WROW     20          // padded W stage row (floats), 80B = 5*16B aligned
#define HROW     260         // padded h row (floats)
#define WSTAGE   (THREE_H * WROW)

__device__ __forceinline__ float sigf(float v) {
    return __fdividef(1.0f, 1.0f + __expf(-v));
}
__device__ __forceinline__ float tanhf2(float v) {
    // tanh(x) = 2*sigmoid(2x) - 1  (accurate: __expf err ~1e-6 rel)
    return fmaf(2.0f, sigf(2.0f * v), -1.0f);
}

__device__ __forceinline__ void issue_block(const float* __restrict__ w_hh,
                                            float* dstbase, int kb, int tid) {
    // stage w_hh[:, kb*16 .. kb*16+15] -> [768][WROW] smem tile. 3072 16B chunks.
#pragma unroll
    for (int r = 0; r < 12; r++) {
        int ch = tid + r * NTHREADS;       // 0..3071
        int j  = ch >> 2;
        int q  = ch & 3;
        const float* src = w_hh + j * HDIM + kb * KB + q * 4;
        unsigned d = (unsigned)__cvta_generic_to_shared(dstbase + j * WROW + q * 4);
        asm volatile("cp.async.cg.shared.global [%0], [%1], 16;\n" :: "r"(d), "l"(src));
    }
    asm volatile("cp.async.commit_group;\n");
}

// One full GEMM step: acc[ci][g][i] = sum_k w_hh[g*256 + c][k] * h[b0+i][k]
// with c = cl + ci*64, b0 = bg*8.
__device__ __forceinline__ void gemm_step(const float* __restrict__ w_hh,
                                          float* Wbuf, const float* __restrict__ rb,
                                          int tid, int bg, int cl,
                                          float (&acc)[4][3][8]) {
#pragma unroll
    for (int ci = 0; ci < 4; ci++)
#pragma unroll
        for (int g = 0; g < 3; g++)
#pragma unroll
            for (int i = 0; i < 8; i++) acc[ci][g][i] = 0.0f;

    issue_block(w_hh, Wbuf, 0, tid);

#pragma unroll 1
    for (int kb = 0; kb < HDIM / KB; kb++) {
        if (kb < HDIM / KB - 1) {
            issue_block(w_hh, Wbuf + ((kb + 1) & 1) * WSTAGE, kb + 1, tid);
            asm volatile("cp.async.wait_group 1;\n");
        } else {
            asm volatile("cp.async.wait_group 0;\n");
        }
        __syncthreads();   // all threads' staged data visible

        const float* cur = Wbuf + (kb & 1) * WSTAGE;
#pragma unroll 2
        for (int kq = 0; kq < 4; kq++) {
            float4 hq[8];
#pragma unroll
            for (int i = 0; i < 8; i++)
                hq[i] = *reinterpret_cast<const float4*>(
                    &rb[(bg * 8 + i) * HROW + kb * KB + kq * 4]);
#pragma unroll
            for (int ci = 0; ci < 4; ci++) {
                int c = cl + ci * 64;
#pragma unroll
                for (int g = 0; g < 3; g++) {
                    const float4 wq = *reinterpret_cast<const float4*>(
                        &cur[(g * 256 + c) * WROW + kq * 4]);
#pragma unroll
                    for (int i = 0; i < 8; i++) {
                        float a = acc[ci][g][i];
                        a = fmaf(wq.x, hq[i].x, a);
                        a = fmaf(wq.y, hq[i].y, a);
                        a = fmaf(wq.z, hq[i].z, a);
                        a = fmaf(wq.w, hq[i].w, a);
                        acc[ci][g][i] = a;
                    }
                }
            }
        }
        __syncthreads();   // tile fully consumed before next overwrite
    }
}

__global__ __launch_bounds__(NTHREADS, 1)
void gru_kernel(const float* __restrict__ gx, const float* __restrict__ w_ih,
                const float* __restrict__ w_hh, const float* __restrict__ b_ih,
                const float* __restrict__ b_hh, const float* __restrict__ w_out,
                const float* __restrict__ b_out, float* __restrict__ out, int TL) {
    extern __shared__ float sm[];
    float* h0     = sm;                        // [TB][HROW]
    float* h1     = h0 + TB * HROW;            // [TB][HROW]
    float* Wbuf   = h1 + TB * HROW;            // 2 * [768][WROW]
    float* u_s    = Wbuf + 2 * WSTAGE;         // [768]  (w_ih[:,0])
    float* bih_s  = u_s + THREE_H;             // [768]
    float* bhh_s  = bih_s + THREE_H;           // [768]
    float* wout_s = bhh_s + THREE_H;           // [256]
    float* x_s    = wout_s + HDIM;             // [TB][SEQ]
    float* red    = x_s + TB * SEQ;            // [TB][72]
    float* outs   = red + TB * 72;             // [TB]

    const int tid = threadIdx.x;
    const int bg  = tid >> 6;     // 0..3 -> batch group of 8
    const int cl  = tid & 63;     // 0..63 -> hidden-unit lane
    const int b0  = bg * 8;
    const int gb0 = blockIdx.x * TB;

    // ---- init: zero h0, cache params + x tile ----
    for (int i = tid; i < TB * HROW; i += NTHREADS) h0[i] = 0.0f;
    for (int i = tid; i < THREE_H; i += NTHREADS) {
        u_s[i]   = w_ih[i];     // [3H,1] contiguous
        bih_s[i] = b_ih[i];
        bhh_s[i] = b_hh[i];
    }
    for (int i = tid; i < HDIM; i += NTHREADS) wout_s[i] = w_out[i];
    for (int i = tid; i < TB * SEQ; i += NTHREADS) {
        int b = i >> 6, t = i & 63;
        x_s[i] = gx[(gb0 + b) * SEQ + t];
    }
    __syncthreads();

    float acc[4][3][8];

    // ---- encoder: 64 GRU steps, h ping-pongs h0 <-> h1 ----
#pragma unroll 1
    for (int t = 0; t < SEQ; t++) {
        const float* rb = (t & 1) ? h1 : h0;
        float*       wb = (t & 1) ? h0 : h1;
        gemm_step(w_hh, Wbuf, rb, tid, bg, cl, acc);
#pragma unroll
        for (int ci = 0; ci < 4; ci++) {
            int c = cl + ci * 64;
            float ur = u_s[c], uz = u_s[c + 256], un = u_s[c + 512];
            float br = bih_s[c] + bhh_s[c];
            float bz = bih_s[c + 256] + bhh_s[c + 256];
            float bin = bih_s[c + 512], bhn = bhh_s[c + 512];
#pragma unroll
            for (int i = 0; i < 8; i++) {
                int b = b0 + i;
                float xv = x_s[b * SEQ + t];
                float r = sigf(fmaf(xv, ur, br) + acc[ci][0][i]);
                float z = sigf(fmaf(xv, uz, bz) + acc[ci][1][i]);
                float n = tanhf2(fmaf(xv, un, bin) + r * (acc[ci][2][i] + bhn));
                float hold = rb[b * HROW + c];
                wb[b * HROW + c] = fmaf(z, hold - n, n);   // (1-z)*n + z*h
            }
        }
        __syncthreads();
    }
    // SEQ=64 even -> final hidden lives in h0.

    // ---- gh_dec = w_hh @ hidden + b_hh  (kept in registers as acc) ----
    gemm_step(w_hh, Wbuf, h0, tid, bg, cl, acc);
#pragma unroll
    for (int ci = 0; ci < 4; ci++) {
        int c = cl + ci * 64;
#pragma unroll
        for (int g = 0; g < 3; g++)
#pragma unroll
            for (int i = 0; i < 8; i++)
                acc[ci][g][i] += bhh_s[g * 256 + c];
    }
    // h_t working buffer = h1, init to hidden
    for (int i = tid; i < TB * HROW; i += NTHREADS) h1[i] = h0[i];
    __syncthreads();

    // ---- decoder: TL cheap steps ----
#pragma unroll 1
    for (int t = 0; t < TL; t++) {
        // out[b] = dot(w_out, h_t[b]) + b_out  (64-lane tree reduction per b)
#pragma unroll
        for (int i = 0; i < 8; i++) {
            int b = b0 + i;
            float p = 0.0f;
#pragma unroll
            for (int ci = 0; ci < 4; ci++) {
                int c = cl + ci * 64;
                p = fmaf(wout_s[c], h1[b * HROW + c], p);
            }
            red[b * 72 + cl] = p;
        }
        __syncthreads();
        {
            int b = tid >> 3, seg = tid & 7;
            float s = 0.0f;
#pragma unroll
            for (int j = 0; j < 8; j++) s += red[b * 72 + seg * 8 + j];
            red[b * 72 + 64 + seg] = s;
        }
        __syncthreads();
        if (tid < TB) {
            float s = 0.0f;
#pragma unroll
            for (int j = 0; j < 8; j++) s += red[tid * 72 + 64 + j];
            float o = s + b_out[0];
            outs[tid] = o;
            out[(gb0 + tid) * TL + t] = o;
        }
        __syncthreads();
        // h_{t+1} = gru_cell(out, hidden) with fixed gh_dec (acc)
#pragma unroll
        for (int ci = 0; ci < 4; ci++) {
            int c = cl + ci * 64;
            float ur = u_s[c], uz = u_s[c + 256], un = u_s[c + 512];
            float bir = bih_s[c], biz = bih_s[c + 256], bin = bih_s[c + 512];
#pragma unroll
            for (int i = 0; i < 8; i++) {
                int b = b0 + i;
                float xv = outs[b];
                float r = sigf(fmaf(xv, ur, bir) + acc[ci][0][i]);
                float z = sigf(fmaf(xv, uz, biz) + acc[ci][1][i]);
                float n = tanhf2(fmaf(xv, un, bin) + r * acc[ci][2][i]);
                float hid = h0[b * HROW + c];
                h1[b * HROW + c] = fmaf(z, hid - n, n);
            }
        }
        __syncthreads();
    }
}

extern "C" void kernel_launch(void* const* d_in, const int* in_sizes, int n_in,
                              void* d_out, int out_size) {
    const float* x     = (const float*)d_in[0];
    const float* w_ih  = (const float*)d_in[1];
    const float* w_hh  = (const float*)d_in[2];
    const float* b_ih  = (const float*)d_in[3];
    const float* b_hh  = (const float*)d_in[4];
    const float* w_out = (const float*)d_in[5];
    const float* b_out = (const float*)d_in[6];
    float* out = (float*)d_out;

    int B  = in_sizes[0] / SEQ;        // x has B*S*1 elements
    int TL = out_size / B;             // output is [B, TL, 1]

    int smem_floats = 2 * TB * HROW + 2 * WSTAGE + 3 * THREE_H + HDIM +
                      TB * SEQ + TB * 72 + TB;
    int smem_bytes = smem_floats * (int)sizeof(float);

    cudaFuncSetAttribute(gru_kernel, cudaFuncAttributeMaxDynamicSharedMemorySize,
                         smem_bytes);
    gru_kernel<<<B / TB, NTHREADS, smem_bytes>>>(x, w_ih, w_hh, b_ih, b_hh,
                                                 w_out, b_out, out, TL);
}